// round 13
// baseline (speedup 1.0000x reference)
#include <cuda_runtime.h>
#include <cstdint>

// ---- problem constants ----
#define B_ 4
#define N_ 4
#define D_ 41
#define FH_ 16
#define FW_ 44
#define C_ 64
#define NX_ 240
#define NY_ 240
#define NPTS_ (B_*N_*D_*FH_*FW_)      // 461824
#define NSPAT_ (NY_*NX_)              // 57600
#define OUT_ELEMS_ (B_*C_*NSPAT_)     // 14745600
#define QBATCH_ (NPTS_/B_)            // 115456 = 451*256
#define OBATCH_ (OUT_ELEMS_/B_)       // 3686400 floats

// per-(b,n): invPostRot[9], combine[9], trans[3], post_trans[3]
__device__ float g_mats[B_*N_][24];
// frustum u coordinates (numpy linspace bits)
__device__ float g_utab[FW_];

// non-FMA 3-dot, left-assoc ascending (XLA decomposed-dot semantics)
__device__ __forceinline__ float dot3(float c0, float c1, float c2,
                                      float p0, float p1, float p2) {
    return __fadd_rn(__fadd_rn(__fmul_rn(c0, p0), __fmul_rn(c1, p1)),
                     __fmul_rn(c2, p2));
}

// f32 3x3 inverse via LU (partial pivoting) + triangular solves,
// back-substitution uses reciprocal-of-diagonal MULTIPLY (cuBLAS trsm style).
__device__ __forceinline__ void inv3x3_cublas_f32(const float a[9], float o[9]) {
    float LU[9];
    #pragma unroll
    for (int k = 0; k < 9; k++) LU[k] = a[k];
    int perm[3] = {0, 1, 2};
    #pragma unroll
    for (int k = 0; k < 2; k++) {
        int p = k;
        float best = fabsf(LU[k*3 + k]);
        #pragma unroll
        for (int i = k + 1; i < 3; i++) {
            float v = fabsf(LU[i*3 + k]);
            if (v > best) { best = v; p = i; }
        }
        if (p != k) {
            #pragma unroll
            for (int j = 0; j < 3; j++) {
                float t = LU[k*3 + j]; LU[k*3 + j] = LU[p*3 + j]; LU[p*3 + j] = t;
            }
            int t = perm[k]; perm[k] = perm[p]; perm[p] = t;
        }
        float rkk = __fdiv_rn(1.0f, LU[k*3 + k]);
        #pragma unroll
        for (int i = k + 1; i < 3; i++) {
            float l = __fmul_rn(LU[i*3 + k], rkk);
            LU[i*3 + k] = l;
            #pragma unroll
            for (int j = k + 1; j < 3; j++)
                LU[i*3 + j] = __fadd_rn(LU[i*3 + j], -__fmul_rn(l, LU[k*3 + j]));
        }
    }
    float r0 = __fdiv_rn(1.0f, LU[0]);
    float r1 = __fdiv_rn(1.0f, LU[4]);
    float r2 = __fdiv_rn(1.0f, LU[8]);
    #pragma unroll
    for (int c = 0; c < 3; c++) {
        float y0 = (perm[0] == c) ? 1.0f : 0.0f;
        float y1 = (perm[1] == c) ? 1.0f : 0.0f;
        float y2 = (perm[2] == c) ? 1.0f : 0.0f;
        y1 = __fadd_rn(y1, -__fmul_rn(LU[3], y0));
        y2 = __fadd_rn(y2, -__fmul_rn(LU[6], y0));
        y2 = __fadd_rn(y2, -__fmul_rn(LU[7], y1));
        float x2 = __fmul_rn(y2, r2);
        float x1 = __fmul_rn(__fadd_rn(y1, -__fmul_rn(LU[5], x2)), r1);
        float x0 = __fmul_rn(__fadd_rn(__fadd_rn(y0, -__fmul_rn(LU[1], x1)),
                                       -__fmul_rn(LU[2], x2)), r0);
        o[0*3 + c] = x0; o[1*3 + c] = x1; o[2*3 + c] = x2;
    }
}

// Zero one batch of the output (poisoned 0xAA; untouched voxels must be 0).
// Installs the out lines in L2 so the splat's REDs hit dirty L2 lines.
// do_setup != 0: block 0 also computes the per-camera matrices + u table.
__global__ void __launch_bounds__(256) zero_setup_kernel(
        float* __restrict__ outb, int do_setup,
        const float* __restrict__ rots,
        const float* __restrict__ trans,
        const float* __restrict__ intrins,
        const float* __restrict__ post_rots,
        const float* __restrict__ post_trans) {
    float4* o4 = reinterpret_cast<float4*>(outb);
    int base = blockIdx.x * 256 + threadIdx.x;
    const int stride = 900 * 256;      // grid is 900 blocks; 4*stride = OBATCH_/4
    #pragma unroll
    for (int i = 0; i < 4; i++)
        o4[base + i * stride] = make_float4(0.f, 0.f, 0.f, 0.f);

    if (!do_setup || blockIdx.x != 0) return;
    int i = threadIdx.x;
    if (i < FW_)   // numpy linspace: f64 w*step, endpoint override
        g_utab[i] = (i == FW_-1) ? 703.0f : (float)((double)i * (703.0 / 43.0));
    if (i >= B_*N_) return;
    float A[9], iK[9], ipr[9], R[9];
    #pragma unroll
    for (int k = 0; k < 9; k++) A[k] = intrins[i*9 + k];
    inv3x3_cublas_f32(A, iK);
    #pragma unroll
    for (int k = 0; k < 9; k++) A[k] = post_rots[i*9 + k];
    inv3x3_cublas_f32(A, ipr);
    #pragma unroll
    for (int k = 0; k < 9; k++) R[k] = rots[i*9 + k];

    float* M = g_mats[i];
    #pragma unroll
    for (int k = 0; k < 9; k++) M[k] = ipr[k];
    #pragma unroll
    for (int r = 0; r < 3; r++)
        #pragma unroll
        for (int c = 0; c < 3; c++)
            M[9 + r*3 + c] = dot3(R[r*3+0], R[r*3+1], R[r*3+2],
                                  iK[c], iK[3+c], iK[6+c]);
    M[18] = trans[i*3+0];      M[19] = trans[i*3+1];      M[20] = trans[i*3+2];
    M[21] = post_trans[i*3+0]; M[22] = post_trans[i*3+1]; M[23] = post_trans[i*3+2];
}

__device__ __forceinline__ void red_add_f32(float* p, float v) {
    asm volatile("red.global.add.f32 [%0], %1;" :: "l"(p), "f"(v) : "memory");
}

// Splat (one batch) directly into the channel-major output.
// h-fastest mapping: the 16 points of a group (fixed b,n,d,w; h=0..15) usually
// share one voxel -> presum 16 features, 4 scalar REDs per channel-quad thread.
// Non-uniform groups: run-length sweep over h (extra REDs for split runs are
// still atomically correct).
__global__ void __launch_bounds__(256) splat_kernel(const float* __restrict__ x,
                                                    float* __restrict__ out,
                                                    int qofs) {
    __shared__ int s_lin[256];   // b*C*NSPAT + s, or -1
    __shared__ int s_p0[16];     // point index at h=0 for each group
    __shared__ int s_uni[16];
    int tid = threadIdx.x;
    int q = qofs + blockIdx.x * 256 + tid;

    // ---- phase 1: geometry (bit-identical arithmetic; h-fastest mapping) ----
    {
        int h = q & 15;            // FH_ == 16
        int t = q >> 4;
        int w = t % FW_;  t /= FW_;
        int d = t % D_;
        int bn = t / D_;           // b*N + n
        int b  = bn >> 2;          // N_ == 4
        if (h == 0) s_p0[tid >> 4] = (bn * D_ + d) * (FH_ * FW_) + w;
        const float* M = g_mats[bn];

        float u   = g_utab[w];
        float v   = (float)(h * 17);            // 255/15 == 17 exact
        float dep = 4.0f + (float)d;

        float p0 = __fadd_rn(u,   -M[21]);
        float p1 = __fadd_rn(v,   -M[22]);
        float p2 = __fadd_rn(dep, -M[23]);
        float a0 = dot3(M[0], M[1], M[2], p0, p1, p2);
        float a1 = dot3(M[3], M[4], M[5], p0, p1, p2);
        float a2 = dot3(M[6], M[7], M[8], p0, p1, p2);
        float X = __fmul_rn(a0, a2);
        float Y = __fmul_rn(a1, a2);
        float Z = a2;
        float qx = __fadd_rn(dot3(M[ 9], M[10], M[11], X, Y, Z), M[18]);
        float qy = __fadd_rn(dot3(M[12], M[13], M[14], X, Y, Z), M[19]);
        float qz = __fadd_rn(dot3(M[15], M[16], M[17], X, Y, Z), M[20]);

        int vx = (int)__fdiv_rn(__fadd_rn(qx, 48.0f), 0.4f);
        int vy = (int)__fdiv_rn(__fadd_rn(qy, 48.0f), 0.4f);
        int vz = (int)__fdiv_rn(__fadd_rn(qz, 10.0f), 20.0f);
        bool kept = (vx >= 0) & (vx < NX_) & (vy >= 0) & (vy < NY_) & (vz == 0);
        s_lin[tid] = kept ? (b * (C_*NSPAT_) + vy * NX_ + vx) : -1;
    }
    __syncthreads();

    if ((tid & 15) == 0) {       // group-uniformity check (one thread per group)
        int g16 = tid;
        int l0 = s_lin[g16];
        bool uni = true;
        #pragma unroll
        for (int i = 1; i < 16; i++) uni &= (s_lin[g16 + i] == l0);
        s_uni[tid >> 4] = uni;
    }
    __syncthreads();

    // ---- phase 2: group per 16 threads; thread cq handles channels cq*4..+3 ----
    int g  = tid >> 4;
    int cq = tid & 15;
    int p0 = s_p0[g];
    const float4* x4 = reinterpret_cast<const float4*>(x);
    if (s_uni[g]) {
        int lin = s_lin[g * 16];
        if (lin >= 0) {
            float4 acc = __ldg(x4 + (size_t)p0 * 16 + cq);
            #pragma unroll
            for (int i = 1; i < 16; i++) {
                float4 f = __ldg(x4 + (size_t)(p0 + i * FW_) * 16 + cq);
                acc.x = __fadd_rn(acc.x, f.x);
                acc.y = __fadd_rn(acc.y, f.y);
                acc.z = __fadd_rn(acc.z, f.z);
                acc.w = __fadd_rn(acc.w, f.w);
            }
            float* dst = out + (size_t)lin + (size_t)(cq*4) * NSPAT_;
            red_add_f32(dst + 0*NSPAT_, acc.x);
            red_add_f32(dst + 1*NSPAT_, acc.y);
            red_add_f32(dst + 2*NSPAT_, acc.z);
            red_add_f32(dst + 3*NSPAT_, acc.w);
        }
    } else {
        // run-length sweep over h
        int i = 0;
        #pragma unroll 1
        while (i < 16) {
            int li = s_lin[g*16 + i];
            if (li < 0) { i++; continue; }
            float4 acc = __ldg(x4 + (size_t)(p0 + i * FW_) * 16 + cq);
            int j = i + 1;
            #pragma unroll 1
            while (j < 16 && s_lin[g*16 + j] == li) {
                float4 f = __ldg(x4 + (size_t)(p0 + j * FW_) * 16 + cq);
                acc.x = __fadd_rn(acc.x, f.x);
                acc.y = __fadd_rn(acc.y, f.y);
                acc.z = __fadd_rn(acc.z, f.z);
                acc.w = __fadd_rn(acc.w, f.w);
                j++;
            }
            float* dst = out + (size_t)li + (size_t)(cq*4) * NSPAT_;
            red_add_f32(dst + 0*NSPAT_, acc.x);
            red_add_f32(dst + 1*NSPAT_, acc.y);
            red_add_f32(dst + 2*NSPAT_, acc.z);
            red_add_f32(dst + 3*NSPAT_, acc.w);
            i = j;
        }
    }
}

extern "C" void kernel_launch(void* const* d_in, const int* in_sizes, int n_in,
                              void* d_out, int out_size) {
    const float* x          = (const float*)d_in[0];
    const float* rots       = (const float*)d_in[1];
    const float* trans      = (const float*)d_in[2];
    const float* intrins    = (const float*)d_in[3];
    const float* post_rots  = (const float*)d_in[4];
    const float* post_trans = (const float*)d_in[5];
    float* out = (float*)d_out;

    // Two-stream pipeline: zero batch b (main/default stream) unblocks splat
    // batch b (side stream). Zero (L2-write-bound) hides under splat
    // (DRAM-read-bound). Fork/join via events -> valid graph-capture topology.
    cudaStream_t s1;
    cudaStreamCreate(&s1);
    cudaEvent_t evZ[B_], evF;
    for (int b = 0; b < B_; b++) {
        zero_setup_kernel<<<900, 256>>>(out + (size_t)b * OBATCH_, b == 0,
                                        rots, trans, intrins, post_rots, post_trans);
        cudaEventCreateWithFlags(&evZ[b], cudaEventDisableTiming);
        cudaEventRecord(evZ[b], 0);
        cudaStreamWaitEvent(s1, evZ[b], 0);
        splat_kernel<<<QBATCH_/256, 256, 0, s1>>>(x, out, b * QBATCH_);
    }
    cudaEventCreateWithFlags(&evF, cudaEventDisableTiming);
    cudaEventRecord(evF, s1);
    cudaStreamWaitEvent(0, evF, 0);
    // join complete: side stream's capture segment is closed; safe to release
    for (int b = 0; b < B_; b++) cudaEventDestroy(evZ[b]);
    cudaEventDestroy(evF);
    cudaStreamDestroy(s1);
}

// round 14
// speedup vs baseline: 1.7728x; 1.7728x over previous
#include <cuda_runtime.h>
#include <cstdint>

// ---- problem constants ----
#define B_ 4
#define N_ 4
#define D_ 41
#define FH_ 16
#define FW_ 44
#define C_ 64
#define NX_ 240
#define NY_ 240
#define NPTS_ (B_*N_*D_*FH_*FW_)      // 461824
#define NSPAT_ (NY_*NX_)              // 57600
#define OUT_ELEMS_ (B_*C_*NSPAT_)     // 14745600

// per-(b,n): invPostRot[9], combine[9], trans[3], post_trans[3]
__device__ float g_mats[B_*N_][24];
// frustum u coordinates (numpy linspace bits)
__device__ float g_utab[FW_];

// non-FMA 3-dot, left-assoc ascending (XLA decomposed-dot semantics)
__device__ __forceinline__ float dot3(float c0, float c1, float c2,
                                      float p0, float p1, float p2) {
    return __fadd_rn(__fadd_rn(__fmul_rn(c0, p0), __fmul_rn(c1, p1)),
                     __fmul_rn(c2, p2));
}

// f32 3x3 inverse via LU (partial pivoting) + triangular solves,
// back-substitution uses reciprocal-of-diagonal MULTIPLY (cuBLAS trsm style).
__device__ __forceinline__ void inv3x3_cublas_f32(const float a[9], float o[9]) {
    float LU[9];
    #pragma unroll
    for (int k = 0; k < 9; k++) LU[k] = a[k];
    int perm[3] = {0, 1, 2};
    #pragma unroll
    for (int k = 0; k < 2; k++) {
        int p = k;
        float best = fabsf(LU[k*3 + k]);
        #pragma unroll
        for (int i = k + 1; i < 3; i++) {
            float v = fabsf(LU[i*3 + k]);
            if (v > best) { best = v; p = i; }
        }
        if (p != k) {
            #pragma unroll
            for (int j = 0; j < 3; j++) {
                float t = LU[k*3 + j]; LU[k*3 + j] = LU[p*3 + j]; LU[p*3 + j] = t;
            }
            int t = perm[k]; perm[k] = perm[p]; perm[p] = t;
        }
        float rkk = __fdiv_rn(1.0f, LU[k*3 + k]);
        #pragma unroll
        for (int i = k + 1; i < 3; i++) {
            float l = __fmul_rn(LU[i*3 + k], rkk);
            LU[i*3 + k] = l;
            #pragma unroll
            for (int j = k + 1; j < 3; j++)
                LU[i*3 + j] = __fadd_rn(LU[i*3 + j], -__fmul_rn(l, LU[k*3 + j]));
        }
    }
    float r0 = __fdiv_rn(1.0f, LU[0]);
    float r1 = __fdiv_rn(1.0f, LU[4]);
    float r2 = __fdiv_rn(1.0f, LU[8]);
    #pragma unroll
    for (int c = 0; c < 3; c++) {
        float y0 = (perm[0] == c) ? 1.0f : 0.0f;
        float y1 = (perm[1] == c) ? 1.0f : 0.0f;
        float y2 = (perm[2] == c) ? 1.0f : 0.0f;
        y1 = __fadd_rn(y1, -__fmul_rn(LU[3], y0));
        y2 = __fadd_rn(y2, -__fmul_rn(LU[6], y0));
        y2 = __fadd_rn(y2, -__fmul_rn(LU[7], y1));
        float x2 = __fmul_rn(y2, r2);
        float x1 = __fmul_rn(__fadd_rn(y1, -__fmul_rn(LU[5], x2)), r1);
        float x0 = __fmul_rn(__fadd_rn(__fadd_rn(y0, -__fmul_rn(LU[1], x1)),
                                       -__fmul_rn(LU[2], x2)), r0);
        o[0*3 + c] = x0; o[1*3 + c] = x1; o[2*3 + c] = x2;
    }
}

// Zero the OUTPUT buffer (poisoned 0xAA; untouched voxels must be 0) and
// compute the per-camera matrices in block 0. The zero also installs the out
// lines in L2 so the splat's REDs hit dirty L2 lines.
__global__ void __launch_bounds__(256) zero_setup_kernel(
        float* __restrict__ out,
        const float* __restrict__ rots,
        const float* __restrict__ trans,
        const float* __restrict__ intrins,
        const float* __restrict__ post_rots,
        const float* __restrict__ post_trans) {
    float4* o4 = reinterpret_cast<float4*>(out);
    int base = blockIdx.x * 256 + threadIdx.x;
    const int stride = 3600 * 256;     // grid is 3600 blocks; 4*stride = OUT_ELEMS_/4
    #pragma unroll
    for (int i = 0; i < 4; i++)
        o4[base + i * stride] = make_float4(0.f, 0.f, 0.f, 0.f);

    if (blockIdx.x != 0) return;
    int i = threadIdx.x;
    if (i < FW_)   // numpy linspace: f64 w*step, endpoint override
        g_utab[i] = (i == FW_-1) ? 703.0f : (float)((double)i * (703.0 / 43.0));
    if (i >= B_*N_) return;
    float A[9], iK[9], ipr[9], R[9];
    #pragma unroll
    for (int k = 0; k < 9; k++) A[k] = intrins[i*9 + k];
    inv3x3_cublas_f32(A, iK);
    #pragma unroll
    for (int k = 0; k < 9; k++) A[k] = post_rots[i*9 + k];
    inv3x3_cublas_f32(A, ipr);
    #pragma unroll
    for (int k = 0; k < 9; k++) R[k] = rots[i*9 + k];

    float* M = g_mats[i];
    #pragma unroll
    for (int k = 0; k < 9; k++) M[k] = ipr[k];
    #pragma unroll
    for (int r = 0; r < 3; r++)
        #pragma unroll
        for (int c = 0; c < 3; c++)
            M[9 + r*3 + c] = dot3(R[r*3+0], R[r*3+1], R[r*3+2],
                                  iK[c], iK[3+c], iK[6+c]);
    M[18] = trans[i*3+0];      M[19] = trans[i*3+1];      M[20] = trans[i*3+2];
    M[21] = post_trans[i*3+0]; M[22] = post_trans[i*3+1]; M[23] = post_trans[i*3+2];
}

__device__ __forceinline__ void red_add_f32(float* p, float v) {
    asm volatile("red.global.add.f32 [%0], %1;" :: "l"(p), "f"(v) : "memory");
}

// Splat directly into the channel-major output (full grid, 512-thread blocks).
// h-fastest mapping: the 16 points of a group (fixed b,n,d,w; h=0..15) usually
// share one voxel -> presum 16 features, 4 scalar REDs per channel-quad thread.
// Non-uniform groups: run-length sweep over h. x loads use streaming (__ldcs)
// so the read-once 118MB x stream doesn't evict the L2-resident out lines.
__global__ void __launch_bounds__(512) splat_kernel(const float* __restrict__ x,
                                                    float* __restrict__ out) {
    __shared__ int s_lin[512];   // b*C*NSPAT + s, or -1
    __shared__ int s_p0[32];     // point index at h=0 for each group
    __shared__ int s_uni[32];
    int tid = threadIdx.x;
    int q = blockIdx.x * 512 + tid;

    // ---- phase 1: geometry (bit-identical arithmetic; h-fastest mapping) ----
    {
        int h = q & 15;            // FH_ == 16
        int t = q >> 4;
        int w = t % FW_;  t /= FW_;
        int d = t % D_;
        int bn = t / D_;           // b*N + n
        int b  = bn >> 2;          // N_ == 4
        if (h == 0) s_p0[tid >> 4] = (bn * D_ + d) * (FH_ * FW_) + w;
        const float* M = g_mats[bn];

        float u   = g_utab[w];
        float v   = (float)(h * 17);            // 255/15 == 17 exact
        float dep = 4.0f + (float)d;

        float p0 = __fadd_rn(u,   -M[21]);
        float p1 = __fadd_rn(v,   -M[22]);
        float p2 = __fadd_rn(dep, -M[23]);
        float a0 = dot3(M[0], M[1], M[2], p0, p1, p2);
        float a1 = dot3(M[3], M[4], M[5], p0, p1, p2);
        float a2 = dot3(M[6], M[7], M[8], p0, p1, p2);
        float X = __fmul_rn(a0, a2);
        float Y = __fmul_rn(a1, a2);
        float Z = a2;
        float qx = __fadd_rn(dot3(M[ 9], M[10], M[11], X, Y, Z), M[18]);
        float qy = __fadd_rn(dot3(M[12], M[13], M[14], X, Y, Z), M[19]);
        float qz = __fadd_rn(dot3(M[15], M[16], M[17], X, Y, Z), M[20]);

        int vx = (int)__fdiv_rn(__fadd_rn(qx, 48.0f), 0.4f);
        int vy = (int)__fdiv_rn(__fadd_rn(qy, 48.0f), 0.4f);
        int vz = (int)__fdiv_rn(__fadd_rn(qz, 10.0f), 20.0f);
        bool kept = (vx >= 0) & (vx < NX_) & (vy >= 0) & (vy < NY_) & (vz == 0);
        s_lin[tid] = kept ? (b * (C_*NSPAT_) + vy * NX_ + vx) : -1;
    }
    __syncthreads();

    if ((tid & 15) == 0) {       // group-uniformity check (one thread per group)
        int g16 = tid;
        int l0 = s_lin[g16];
        bool uni = true;
        #pragma unroll
        for (int i = 1; i < 16; i++) uni &= (s_lin[g16 + i] == l0);
        s_uni[tid >> 4] = uni;
    }
    __syncthreads();

    // ---- phase 2: group per 16 threads; thread cq handles channels cq*4..+3 ----
    int g  = tid >> 4;
    int cq = tid & 15;
    int p0 = s_p0[g];
    const float4* x4 = reinterpret_cast<const float4*>(x);
    if (s_uni[g]) {
        int lin = s_lin[g * 16];
        if (lin >= 0) {
            float4 acc = __ldcs(x4 + (size_t)p0 * 16 + cq);
            #pragma unroll
            for (int i = 1; i < 16; i++) {
                float4 f = __ldcs(x4 + (size_t)(p0 + i * FW_) * 16 + cq);
                acc.x = __fadd_rn(acc.x, f.x);
                acc.y = __fadd_rn(acc.y, f.y);
                acc.z = __fadd_rn(acc.z, f.z);
                acc.w = __fadd_rn(acc.w, f.w);
            }
            float* dst = out + (size_t)lin + (size_t)(cq*4) * NSPAT_;
            red_add_f32(dst + 0*NSPAT_, acc.x);
            red_add_f32(dst + 1*NSPAT_, acc.y);
            red_add_f32(dst + 2*NSPAT_, acc.z);
            red_add_f32(dst + 3*NSPAT_, acc.w);
        }
    } else {
        // run-length sweep over h
        int i = 0;
        #pragma unroll 1
        while (i < 16) {
            int li = s_lin[g*16 + i];
            if (li < 0) { i++; continue; }
            float4 acc = __ldcs(x4 + (size_t)(p0 + i * FW_) * 16 + cq);
            int j = i + 1;
            #pragma unroll 1
            while (j < 16 && s_lin[g*16 + j] == li) {
                float4 f = __ldcs(x4 + (size_t)(p0 + j * FW_) * 16 + cq);
                acc.x = __fadd_rn(acc.x, f.x);
                acc.y = __fadd_rn(acc.y, f.y);
                acc.z = __fadd_rn(acc.z, f.z);
                acc.w = __fadd_rn(acc.w, f.w);
                j++;
            }
            float* dst = out + (size_t)li + (size_t)(cq*4) * NSPAT_;
            red_add_f32(dst + 0*NSPAT_, acc.x);
            red_add_f32(dst + 1*NSPAT_, acc.y);
            red_add_f32(dst + 2*NSPAT_, acc.z);
            red_add_f32(dst + 3*NSPAT_, acc.w);
            i = j;
        }
    }
}

extern "C" void kernel_launch(void* const* d_in, const int* in_sizes, int n_in,
                              void* d_out, int out_size) {
    const float* x          = (const float*)d_in[0];
    const float* rots       = (const float*)d_in[1];
    const float* trans      = (const float*)d_in[2];
    const float* intrins    = (const float*)d_in[3];
    const float* post_rots  = (const float*)d_in[4];
    const float* post_trans = (const float*)d_in[5];
    float* out = (float*)d_out;

    zero_setup_kernel<<<3600, 256>>>(out, rots, trans, intrins, post_rots, post_trans);
    splat_kernel<<<NPTS_/512, 512>>>(x, out);
}